// round 7
// baseline (speedup 1.0000x reference)
#include <cuda_runtime.h>

#define NMODELS 128
#define SZ      256
#define BATCH   4096
#define NTILES  4
#define TILE_O  64
#define NT      256

#define W_FLOATS (SZ * TILE_O)                       // 16384 (64 KB)
#define SMEM_BYTES (W_FLOATS * 4 + BATCH * 2 + 32)   // ~72.2 KB -> 3 CTAs/SM

__global__ void __launch_bounds__(NT, 3)
fused_kernel(const float* __restrict__ inp,
             const int*   __restrict__ ids,
             const float* __restrict__ wlut,
             const float* __restrict__ blut,
             float* __restrict__ out)
{
    extern __shared__ float smem[];
    float* w_s = smem;                                // [k][64]
    unsigned short* bucket = (unsigned short*)(w_s + W_FLOATS);
    __shared__ int cnt_s;
    __shared__ int work_s;

    const int t    = threadIdx.x;
    const int lane = t & 31;
    const int m    = blockIdx.x >> 2;
    const int tile = blockIdx.x & 3;
    const int og   = t & 15;       // 4 outputs: og*4 .. og*4+3

    if (t == 0) { cnt_s = 0; work_s = 0; }
    __syncthreads();

    // ---- scan agent_ids -> smem bucket ----
    #pragma unroll 16
    for (int b = t; b < BATCH; b += NT) {
        if (__ldg(&ids[b]) == m) {
            int p = atomicAdd(&cnt_s, 1);
            bucket[p] = (unsigned short)b;
        }
    }

    // ---- load W tile [256][64] into smem ----
    const float* wm = wlut + (size_t)m * SZ * SZ + tile * TILE_O;
    float4* w_s4 = (float4*)w_s;
    #pragma unroll 16
    for (int k = t; k < W_FLOATS / 4; k += NT) {
        int i  = k >> 4;
        int j4 = k & 15;
        w_s4[k] = ((const float4*)(wm + (size_t)i * SZ))[j4];
    }

    const float4 bias = ((const float4*)(blut + m * SZ + tile * TILE_O))[og];

    __syncthreads();
    const int cnt = cnt_s;

    // ---- warp-autonomous sample processing: grab 2 samples at a time ----
    for (;;) {
        int p;
        if (lane == 0) p = atomicAdd(&work_s, 2);
        p = __shfl_sync(0xffffffffu, p, 0);
        if (p >= cnt) break;

        const int  i0 = p;
        const int  i1 = p + 1;
        const bool v1 = i1 < cnt;
        const int  b0 = bucket[i0];
        const int  b1 = bucket[v1 ? i1 : i0];
        const float4* x0 = (const float4*)(inp + (size_t)b0 * SZ);
        const float4* x1 = (const float4*)(inp + (size_t)b1 * SZ);

        float a00 = 0.f, a01 = 0.f, a02 = 0.f, a03 = 0.f;
        float a10 = 0.f, a11 = 0.f, a12 = 0.f, a13 = 0.f;

        #pragma unroll 4
        for (int k4 = 0; k4 < SZ / 4; k4++) {
            float4 xa = __ldg(&x0[k4]);
            float4 xb = __ldg(&x1[k4]);
            const float* wr = &w_s[(k4 * 4) * TILE_O + og * 4];

            float4 w0 = *(const float4*)(wr);
            a00 = fmaf(xa.x, w0.x, a00); a01 = fmaf(xa.x, w0.y, a01);
            a02 = fmaf(xa.x, w0.z, a02); a03 = fmaf(xa.x, w0.w, a03);
            a10 = fmaf(xb.x, w0.x, a10); a11 = fmaf(xb.x, w0.y, a11);
            a12 = fmaf(xb.x, w0.z, a12); a13 = fmaf(xb.x, w0.w, a13);

            float4 w1 = *(const float4*)(wr + TILE_O);
            a00 = fmaf(xa.y, w1.x, a00); a01 = fmaf(xa.y, w1.y, a01);
            a02 = fmaf(xa.y, w1.z, a02); a03 = fmaf(xa.y, w1.w, a03);
            a10 = fmaf(xb.y, w1.x, a10); a11 = fmaf(xb.y, w1.y, a11);
            a12 = fmaf(xb.y, w1.z, a12); a13 = fmaf(xb.y, w1.w, a13);

            float4 w2 = *(const float4*)(wr + 2 * TILE_O);
            a00 = fmaf(xa.z, w2.x, a00); a01 = fmaf(xa.z, w2.y, a01);
            a02 = fmaf(xa.z, w2.z, a02); a03 = fmaf(xa.z, w2.w, a03);
            a10 = fmaf(xb.z, w2.x, a10); a11 = fmaf(xb.z, w2.y, a11);
            a12 = fmaf(xb.z, w2.z, a12); a13 = fmaf(xb.z, w2.w, a13);

            float4 w3 = *(const float4*)(wr + 3 * TILE_O);
            a00 = fmaf(xa.w, w3.x, a00); a01 = fmaf(xa.w, w3.y, a01);
            a02 = fmaf(xa.w, w3.z, a02); a03 = fmaf(xa.w, w3.w, a03);
            a10 = fmaf(xb.w, w3.x, a10); a11 = fmaf(xb.w, w3.y, a11);
            a12 = fmaf(xb.w, w3.z, a12); a13 = fmaf(xb.w, w3.w, a13);
        }

        {
            float4 r = make_float4(a00 + bias.x, a01 + bias.y,
                                   a02 + bias.z, a03 + bias.w);
            ((float4*)(out + (size_t)b0 * SZ + tile * TILE_O))[og] = r;
        }
        if (v1) {
            float4 r = make_float4(a10 + bias.x, a11 + bias.y,
                                   a12 + bias.z, a13 + bias.w);
            ((float4*)(out + (size_t)b1 * SZ + tile * TILE_O))[og] = r;
        }
    }
}

extern "C" void kernel_launch(void* const* d_in, const int* in_sizes, int n_in,
                              void* d_out, int out_size) {
    const float* inp  = (const float*)d_in[0];
    const int*   ids  = (const int*)  d_in[1];
    const float* wlut = (const float*)d_in[2];
    const float* blut = (const float*)d_in[3];
    float* out = (float*)d_out;

    cudaFuncSetAttribute(fused_kernel,
                         cudaFuncAttributeMaxDynamicSharedMemorySize, SMEM_BYTES);

    fused_kernel<<<NMODELS * NTILES, NT, SMEM_BYTES>>>(inp, ids, wlut, blut, out);
}

// round 8
// speedup vs baseline: 2.0936x; 2.0936x over previous
#include <cuda_runtime.h>

#define NMODELS 128
#define SZ      256
#define BATCH   4096
#define NTILES  4
#define TILE_O  64
#define NT      256
#define CH      8

#define XPITCH  260
#define X_FLOATS    (CH * XPITCH)          // 2080
#define PART_FLOATS (CH * TILE_O * 9)      // 4608
#define SMEM_BYTES  ((X_FLOATS + PART_FLOATS + 64) * 4 + BATCH * 2 + 16)  // ~35.2 KB

__global__ void __launch_bounds__(NT, 2)
fused_kernel(const float* __restrict__ inp,
             const int*   __restrict__ ids,
             const float* __restrict__ wlut,
             const float* __restrict__ blut,
             float* __restrict__ out)
{
    extern __shared__ float smem[];
    float* x_s    = smem;                         // [s][XPITCH]
    float* part   = x_s + X_FLOATS;               // [(s*64+o)*9 + kp]
    float* bias_s = part + PART_FLOATS;           // [64]
    unsigned short* bucket = (unsigned short*)(bias_s + 64);
    __shared__ int cnt_s;

    const int t    = threadIdx.x;
    const int og   = t & 15;        // 4 outputs: og*4..+3
    const int ks   = t >> 4;        // k-slice: ks*16..+15
    const int lane = t & 31;
    const int kp   = ks >> 1;       // partial slot 0..7

    const int m    = blockIdx.x >> 2;
    const int tile = blockIdx.x & 3;

    if (t == 0) cnt_s = 0;
    __syncthreads();

    // ---- scan agent_ids -> smem bucket ----
    #pragma unroll 16
    for (int b = t; b < BATCH; b += NT) {
        if (__ldg(&ids[b]) == m) {
            int p = atomicAdd(&cnt_s, 1);
            bucket[p] = (unsigned short)b;
        }
    }

    // ---- load this thread's W block into REGISTERS (16 x float4) ----
    float4 wreg[16];
    {
        const float* wp = wlut + (size_t)m * SZ * SZ + (size_t)(ks * 16) * SZ
                          + tile * TILE_O + og * 4;
        #pragma unroll
        for (int i = 0; i < 16; i++)
            wreg[i] = __ldg((const float4*)(wp + (size_t)i * SZ));
    }

    // ---- bias tile into smem ----
    if (t < 16)
        ((float4*)bias_s)[t] = __ldg(&((const float4*)(blut + m * SZ + tile * TILE_O))[t]);

    __syncthreads();
    const int cnt = cnt_s;
    if (cnt == 0) return;

    for (int s0 = 0; s0 < cnt; s0 += CH) {
        // ---- stage gathered x rows (no zero-pad; invalid slots discarded later) ----
        #pragma unroll
        for (int k = t; k < CH * SZ / 4; k += NT) {
            int s   = k >> 6;
            int i4  = k & 63;
            int idx = s0 + s;
            if (idx < cnt) {
                float4 v = __ldg(&((const float4*)(inp + (size_t)bucket[idx] * SZ))[i4]);
                *(float4*)&x_s[s * XPITCH + i4 * 4] = v;
            }
        }
        __syncthreads();

        // ---- compute: W in regs, x from smem; 16 k x 4 outs x CH samples ----
        float4 acc[CH];
        const float* xbase = &x_s[ks * 16];
        #pragma unroll
        for (int s = 0; s < CH; s++) {
            float4 x0 = *(const float4*)&xbase[s * XPITCH];
            float4 x1 = *(const float4*)&xbase[s * XPITCH + 4];
            float4 x2 = *(const float4*)&xbase[s * XPITCH + 8];
            float4 x3 = *(const float4*)&xbase[s * XPITCH + 12];
            float4 a;
            a.x = x0.x * wreg[0].x; a.y = x0.x * wreg[0].y;
            a.z = x0.x * wreg[0].z; a.w = x0.x * wreg[0].w;
            a.x = fmaf(x0.y, wreg[1].x, a.x); a.y = fmaf(x0.y, wreg[1].y, a.y);
            a.z = fmaf(x0.y, wreg[1].z, a.z); a.w = fmaf(x0.y, wreg[1].w, a.w);
            a.x = fmaf(x0.z, wreg[2].x, a.x); a.y = fmaf(x0.z, wreg[2].y, a.y);
            a.z = fmaf(x0.z, wreg[2].z, a.z); a.w = fmaf(x0.z, wreg[2].w, a.w);
            a.x = fmaf(x0.w, wreg[3].x, a.x); a.y = fmaf(x0.w, wreg[3].y, a.y);
            a.z = fmaf(x0.w, wreg[3].z, a.z); a.w = fmaf(x0.w, wreg[3].w, a.w);

            a.x = fmaf(x1.x, wreg[4].x, a.x); a.y = fmaf(x1.x, wreg[4].y, a.y);
            a.z = fmaf(x1.x, wreg[4].z, a.z); a.w = fmaf(x1.x, wreg[4].w, a.w);
            a.x = fmaf(x1.y, wreg[5].x, a.x); a.y = fmaf(x1.y, wreg[5].y, a.y);
            a.z = fmaf(x1.y, wreg[5].z, a.z); a.w = fmaf(x1.y, wreg[5].w, a.w);
            a.x = fmaf(x1.z, wreg[6].x, a.x); a.y = fmaf(x1.z, wreg[6].y, a.y);
            a.z = fmaf(x1.z, wreg[6].z, a.z); a.w = fmaf(x1.z, wreg[6].w, a.w);
            a.x = fmaf(x1.w, wreg[7].x, a.x); a.y = fmaf(x1.w, wreg[7].y, a.y);
            a.z = fmaf(x1.w, wreg[7].z, a.z); a.w = fmaf(x1.w, wreg[7].w, a.w);

            a.x = fmaf(x2.x, wreg[8].x, a.x); a.y = fmaf(x2.x, wreg[8].y, a.y);
            a.z = fmaf(x2.x, wreg[8].z, a.z); a.w = fmaf(x2.x, wreg[8].w, a.w);
            a.x = fmaf(x2.y, wreg[9].x, a.x); a.y = fmaf(x2.y, wreg[9].y, a.y);
            a.z = fmaf(x2.y, wreg[9].z, a.z); a.w = fmaf(x2.y, wreg[9].w, a.w);
            a.x = fmaf(x2.z, wreg[10].x, a.x); a.y = fmaf(x2.z, wreg[10].y, a.y);
            a.z = fmaf(x2.z, wreg[10].z, a.z); a.w = fmaf(x2.z, wreg[10].w, a.w);
            a.x = fmaf(x2.w, wreg[11].x, a.x); a.y = fmaf(x2.w, wreg[11].y, a.y);
            a.z = fmaf(x2.w, wreg[11].z, a.z); a.w = fmaf(x2.w, wreg[11].w, a.w);

            a.x = fmaf(x3.x, wreg[12].x, a.x); a.y = fmaf(x3.x, wreg[12].y, a.y);
            a.z = fmaf(x3.x, wreg[12].z, a.z); a.w = fmaf(x3.x, wreg[12].w, a.w);
            a.x = fmaf(x3.y, wreg[13].x, a.x); a.y = fmaf(x3.y, wreg[13].y, a.y);
            a.z = fmaf(x3.y, wreg[13].z, a.z); a.w = fmaf(x3.y, wreg[13].w, a.w);
            a.x = fmaf(x3.z, wreg[14].x, a.x); a.y = fmaf(x3.z, wreg[14].y, a.y);
            a.z = fmaf(x3.z, wreg[14].z, a.z); a.w = fmaf(x3.z, wreg[14].w, a.w);
            a.x = fmaf(x3.w, wreg[15].x, a.x); a.y = fmaf(x3.w, wreg[15].y, a.y);
            a.z = fmaf(x3.w, wreg[15].z, a.z); a.w = fmaf(x3.w, wreg[15].w, a.w);
            acc[s] = a;
        }

        // ---- reduce: shfl-combine ks pairs, write 8 partials ----
        #pragma unroll
        for (int s = 0; s < CH; s++) {
            float vx = acc[s].x, vy = acc[s].y, vz = acc[s].z, vw = acc[s].w;
            vx += __shfl_down_sync(0xffffffffu, vx, 16);
            vy += __shfl_down_sync(0xffffffffu, vy, 16);
            vz += __shfl_down_sync(0xffffffffu, vz, 16);
            vw += __shfl_down_sync(0xffffffffu, vw, 16);
            if (lane < 16) {
                int o = og * 4;
                part[(s * TILE_O + o + 0) * 9 + kp] = vx;
                part[(s * TILE_O + o + 1) * 9 + kp] = vy;
                part[(s * TILE_O + o + 2) * 9 + kp] = vz;
                part[(s * TILE_O + o + 3) * 9 + kp] = vw;
            }
        }
        __syncthreads();

        // ---- final: sum 8 partials + bias, store ----
        #pragma unroll
        for (int p = t; p < CH * TILE_O; p += NT) {
            int s = p >> 6;
            int o = p & 63;
            if (s0 + s < cnt) {
                float sum = bias_s[o];
                const float* pp = &part[p * 9];
                #pragma unroll
                for (int g = 0; g < 8; g++) sum += pp[g];
                out[(size_t)bucket[s0 + s] * SZ + tile * TILE_O + o] = sum;
            }
        }
        __syncthreads();
    }
}

extern "C" void kernel_launch(void* const* d_in, const int* in_sizes, int n_in,
                              void* d_out, int out_size) {
    const float* inp  = (const float*)d_in[0];
    const int*   ids  = (const int*)  d_in[1];
    const float* wlut = (const float*)d_in[2];
    const float* blut = (const float*)d_in[3];
    float* out = (float*)d_out;

    cudaFuncSetAttribute(fused_kernel,
                         cudaFuncAttributeMaxDynamicSharedMemorySize, SMEM_BYTES);

    fused_kernel<<<NMODELS * NTILES, NT, SMEM_BYTES>>>(inp, ids, wlut, blut, out);
}

// round 10
// speedup vs baseline: 2.2459x; 1.0727x over previous
#include <cuda_runtime.h>
#include <cstdint>

#define NMODELS 128
#define SZ      256
#define BATCH   4096
#define NT      256
#define TILE_O  64
#define CH      8

#define XPITCH  260
#define X_FLOATS    (CH * XPITCH)          // 2080 per buffer
#define PART_FLOATS (CH * TILE_O * 9)      // 4608
#define SMEM_BYTES  ((2 * X_FLOATS + PART_FLOATS + 64) * 4 + BATCH * 2 + 16)

__device__ __forceinline__ uint32_t smem_u32(const void* p) {
    uint32_t a;
    asm("{ .reg .u64 t; cvta.to.shared.u64 t, %1; cvt.u32.u64 %0, t; }"
        : "=r"(a) : "l"(p));
    return a;
}
__device__ __forceinline__ void cp16(uint32_t dst, const void* src) {
    asm volatile("cp.async.cg.shared.global [%0], [%1], 16;"
                 :: "r"(dst), "l"(src));
}

__global__ void __launch_bounds__(NT, 2)
fused_kernel(const float* __restrict__ inp,
             const int*   __restrict__ ids,
             const float* __restrict__ wlut,
             const float* __restrict__ blut,
             float* __restrict__ out)
{
    extern __shared__ float smem[];
    float* x0_s   = smem;                          // [CH][XPITCH] ping
    float* x1_s   = x0_s + X_FLOATS;               // pong
    float* part   = x1_s + X_FLOATS;               // [(s*64+o)*9 + kp]
    float* bias_s = part + PART_FLOATS;            // [64]
    unsigned short* bucket = (unsigned short*)(bias_s + 64);
    __shared__ int cnt_s;

    const int t    = threadIdx.x;
    const int og   = t & 15;        // 4 outputs: og*4..+3
    const int ks   = t >> 4;        // k-slice: ks*16..+15
    const int lane = t & 31;
    const int kp   = ks >> 1;       // partial slot 0..7

    const int m    = blockIdx.x >> 2;
    const int tile = blockIdx.x & 3;

    if (t == 0) cnt_s = 0;
    __syncthreads();

    // ---- scan agent_ids -> smem bucket ----
    #pragma unroll 16
    for (int b = t; b < BATCH; b += NT) {
        if (__ldg(&ids[b]) == m) {
            int p = atomicAdd(&cnt_s, 1);
            bucket[p] = (unsigned short)b;
        }
    }

    // ---- this thread's W block into registers (16 x float4) ----
    float4 wreg[16];
    {
        const float* wp = wlut + (size_t)m * SZ * SZ + (size_t)(ks * 16) * SZ
                          + tile * TILE_O + og * 4;
        #pragma unroll
        for (int i = 0; i < 16; i++)
            wreg[i] = __ldg((const float4*)(wp + (size_t)i * SZ));
    }

    if (t < 16)
        ((float4*)bias_s)[t] = __ldg(&((const float4*)(blut + m * SZ + tile * TILE_O))[t]);

    __syncthreads();
    const int cnt = cnt_s;
    if (cnt == 0) return;

    // ---- async prefetch of chunk s0 into xbuf ----
    auto prefetch = [&](int s0, float* xbuf) {
        #pragma unroll
        for (int i = 0; i < 2; i++) {
            int k  = t + i * NT;                 // 0..511
            int s  = k >> 6;
            int i4 = k & 63;
            int idx = min(s0 + s, cnt - 1);      // clamp; extra rows discarded
            const float4* src = (const float4*)(inp + (size_t)bucket[idx] * SZ) + i4;
            cp16(smem_u32(&xbuf[s * XPITCH + i4 * 4]), src);
        }
        asm volatile("cp.async.commit_group;" ::: "memory");
    };

    prefetch(0, x0_s);

    for (int s0 = 0, c = 0; s0 < cnt; s0 += CH, c++) {
        float* xb = (c & 1) ? x1_s : x0_s;
        float* xn = (c & 1) ? x0_s : x1_s;

        asm volatile("cp.async.wait_group 0;" ::: "memory");
        __syncthreads();   // xb visible; also orders prev final-reads vs part-writes

        if (s0 + CH < cnt) prefetch(s0 + CH, xn);   // overlap with compute

        // ---- compute: W in regs, x from smem; 16 k x 4 outs x CH samples ----
        float4 acc[CH];
        const float* xbase = &xb[ks * 16];
        #pragma unroll
        for (int s = 0; s < CH; s++) {
            float4 x0 = *(const float4*)&xbase[s * XPITCH];
            float4 x1 = *(const float4*)&xbase[s * XPITCH + 4];
            float4 x2 = *(const float4*)&xbase[s * XPITCH + 8];
            float4 x3 = *(const float4*)&xbase[s * XPITCH + 12];
            float4 a;
            a.x = x0.x * wreg[0].x; a.y = x0.x * wreg[0].y;
            a.z = x0.x * wreg[0].z; a.w = x0.x * wreg[0].w;
            a.x = fmaf(x0.y, wreg[1].x, a.x); a.y = fmaf(x0.y, wreg[1].y, a.y);
            a.z = fmaf(x0.y, wreg[1].z, a.z); a.w = fmaf(x0.y, wreg[1].w, a.w);
            a.x = fmaf(x0.z, wreg[2].x, a.x); a.y = fmaf(x0.z, wreg[2].y, a.y);
            a.z = fmaf(x0.z, wreg[2].z, a.z); a.w = fmaf(x0.z, wreg[2].w, a.w);
            a.x = fmaf(x0.w, wreg[3].x, a.x); a.y = fmaf(x0.w, wreg[3].y, a.y);
            a.z = fmaf(x0.w, wreg[3].z, a.z); a.w = fmaf(x0.w, wreg[3].w, a.w);

            a.x = fmaf(x1.x, wreg[4].x, a.x); a.y = fmaf(x1.x, wreg[4].y, a.y);
            a.z = fmaf(x1.x, wreg[4].z, a.z); a.w = fmaf(x1.x, wreg[4].w, a.w);
            a.x = fmaf(x1.y, wreg[5].x, a.x); a.y = fmaf(x1.y, wreg[5].y, a.y);
            a.z = fmaf(x1.y, wreg[5].z, a.z); a.w = fmaf(x1.y, wreg[5].w, a.w);
            a.x = fmaf(x1.z, wreg[6].x, a.x); a.y = fmaf(x1.z, wreg[6].y, a.y);
            a.z = fmaf(x1.z, wreg[6].z, a.z); a.w = fmaf(x1.z, wreg[6].w, a.w);
            a.x = fmaf(x1.w, wreg[7].x, a.x); a.y = fmaf(x1.w, wreg[7].y, a.y);
            a.z = fmaf(x1.w, wreg[7].z, a.z); a.w = fmaf(x1.w, wreg[7].w, a.w);

            a.x = fmaf(x2.x, wreg[8].x, a.x); a.y = fmaf(x2.x, wreg[8].y, a.y);
            a.z = fmaf(x2.x, wreg[8].z, a.z); a.w = fmaf(x2.x, wreg[8].w, a.w);
            a.x = fmaf(x2.y, wreg[9].x, a.x); a.y = fmaf(x2.y, wreg[9].y, a.y);
            a.z = fmaf(x2.y, wreg[9].z, a.z); a.w = fmaf(x2.y, wreg[9].w, a.w);
            a.x = fmaf(x2.z, wreg[10].x, a.x); a.y = fmaf(x2.z, wreg[10].y, a.y);
            a.z = fmaf(x2.z, wreg[10].z, a.z); a.w = fmaf(x2.z, wreg[10].w, a.w);
            a.x = fmaf(x2.w, wreg[11].x, a.x); a.y = fmaf(x2.w, wreg[11].y, a.y);
            a.z = fmaf(x2.w, wreg[11].z, a.z); a.w = fmaf(x2.w, wreg[11].w, a.w);

            a.x = fmaf(x3.x, wreg[12].x, a.x); a.y = fmaf(x3.x, wreg[12].y, a.y);
            a.z = fmaf(x3.x, wreg[12].z, a.z); a.w = fmaf(x3.x, wreg[12].w, a.w);
            a.x = fmaf(x3.y, wreg[13].x, a.x); a.y = fmaf(x3.y, wreg[13].y, a.y);
            a.z = fmaf(x3.y, wreg[13].z, a.z); a.w = fmaf(x3.y, wreg[13].w, a.w);
            a.x = fmaf(x3.z, wreg[14].x, a.x); a.y = fmaf(x3.z, wreg[14].y, a.y);
            a.z = fmaf(x3.z, wreg[14].z, a.z); a.w = fmaf(x3.z, wreg[14].w, a.w);
            a.x = fmaf(x3.w, wreg[15].x, a.x); a.y = fmaf(x3.w, wreg[15].y, a.y);
            a.z = fmaf(x3.w, wreg[15].z, a.z); a.w = fmaf(x3.w, wreg[15].w, a.w);
            acc[s] = a;
        }

        // ---- reduce: shfl-combine ks pairs, write 8 partials ----
        #pragma unroll
        for (int s = 0; s < CH; s++) {
            float vx = acc[s].x, vy = acc[s].y, vz = acc[s].z, vw = acc[s].w;
            vx += __shfl_down_sync(0xffffffffu, vx, 16);
            vy += __shfl_down_sync(0xffffffffu, vy, 16);
            vz += __shfl_down_sync(0xffffffffu, vz, 16);
            vw += __shfl_down_sync(0xffffffffu, vw, 16);
            if (lane < 16) {
                int o = og * 4;
                part[(s * TILE_O + o + 0) * 9 + kp] = vx;
                part[(s * TILE_O + o + 1) * 9 + kp] = vy;
                part[(s * TILE_O + o + 2) * 9 + kp] = vz;
                part[(s * TILE_O + o + 3) * 9 + kp] = vw;
            }
        }
        __syncthreads();

        // ---- final: 2 consecutive outputs per thread, STG.64 ----
        {
            int p0 = 2 * t;               // 0..510
            int s  = p0 >> 6;
            int o  = p0 & 63;
            if (s0 + s < cnt) {
                const float* pp = &part[(s * TILE_O + o) * 9];
                float sum0 = bias_s[o];
                float sum1 = bias_s[o + 1];
                #pragma unroll
                for (int g = 0; g < 8; g++) { sum0 += pp[g]; sum1 += pp[9 + g]; }
                *(float2*)(out + (size_t)bucket[s0 + s] * SZ + tile * TILE_O + o)
                    = make_float2(sum0, sum1);
            }
        }
        // no trailing barrier: next iteration's top sync orders part reuse
    }
}

extern "C" void kernel_launch(void* const* d_in, const int* in_sizes, int n_in,
                              void* d_out, int out_size) {
    const float* inp  = (const float*)d_in[0];
    const int*   ids  = (const int*)  d_in[1];
    const float* wlut = (const float*)d_in[2];
    const float* blut = (const float*)d_in[3];
    float* out = (float*)d_out;

    cudaFuncSetAttribute(fused_kernel,
                         cudaFuncAttributeMaxDynamicSharedMemorySize, SMEM_BYTES);

    fused_kernel<<<NMODELS * 4, NT, SMEM_BYTES>>>(inp, ids, wlut, blut, out);
}